// round 8
// baseline (speedup 1.0000x reference)
#include <cuda_runtime.h>
#include <cstdint>

// Sparse 3D conv via warp-level fp16 mma.sync (m16n8k16), single pass.
// R7: gather rows staged through a warp-private 2-stage cp.async smem ring
// (zero registers spent on prefetch, full-iteration latency cover, masked
// rows zero-filled via cp.async src_size=0). Row indices distributed by
// shuffle from one coalesced idx+mask load per iter. Smem XOR-swizzled.

static constexpr int kMVox = 100000;
static constexpr int kKVol = 27;
static constexpr int kCIn  = 32;
static constexpr int kCOut = 64;
static constexpr int M_TILE = 128;     // 8 warps x 16 rows
static constexpr int NW = 8;

// B fragments, fp16, fragment-order with K-permutation:
// [koff][nb][lane] -> uint4 {ks0.b0, ks0.b1, ks1.b0, ks1.b1}
__device__ __align__(16) uint4 g_bfrag[kKVol * 8 * 32];

__device__ __forceinline__ unsigned f16x2(float x, float y) {
    unsigned r;
    asm("cvt.rn.f16x2.f32 %0, %1, %2;" : "=r"(r) : "f"(y), "f"(x));  // x -> low half
    return r;
}

__global__ void prep_kernel(const float* __restrict__ kw) {
    int koff = blockIdx.x, tid = threadIdx.x;       // 27 x 256
    int nb = tid >> 5, lane = tid & 31;
    int g = lane >> 2, t = lane & 3;
    int n = nb * 8 + g;
    const float* W = kw + koff * kCIn * kCOut;      // W[i][n]
    uint4 v;
    v.x = f16x2(W[(8 * t + 0) * kCOut + n], W[(8 * t + 1) * kCOut + n]);
    v.y = f16x2(W[(8 * t + 2) * kCOut + n], W[(8 * t + 3) * kCOut + n]);
    v.z = f16x2(W[(8 * t + 4) * kCOut + n], W[(8 * t + 5) * kCOut + n]);
    v.w = f16x2(W[(8 * t + 6) * kCOut + n], W[(8 * t + 7) * kCOut + n]);
    g_bfrag[(koff * 8 + nb) * 32 + lane] = v;
}

__device__ __forceinline__ void mma16816(float* d, const unsigned* a,
                                         unsigned b0, unsigned b1) {
    asm volatile(
        "mma.sync.aligned.m16n8k16.row.col.f32.f16.f16.f32 "
        "{%0,%1,%2,%3}, {%4,%5,%6,%7}, {%8,%9}, {%0,%1,%2,%3};"
        : "+f"(d[0]), "+f"(d[1]), "+f"(d[2]), "+f"(d[3])
        : "r"(a[0]), "r"(a[1]), "r"(a[2]), "r"(a[3]), "r"(b0), "r"(b1));
}

__device__ __forceinline__ float4 lds128(uint32_t addr) {
    float4 v;
    asm volatile("ld.shared.v4.f32 {%0,%1,%2,%3}, [%4];"
                 : "=f"(v.x), "=f"(v.y), "=f"(v.z), "=f"(v.w) : "r"(addr));
    return v;
}

__global__ __launch_bounds__(256, 3)
void conv_hmma_kernel(const float* __restrict__ feats,
                      const int*   __restrict__ in_idx,
                      const int*   __restrict__ mask,
                      float*       __restrict__ out) {
    __shared__ __align__(16) char stage[2][NW][16 * 128];   // 32 KB: 2-stage x warp x 16 rows
    const int w = threadIdx.x >> 5, lane = threadIdx.x & 31;
    const int g = lane >> 2, t = lane & 3;
    const int wbase = blockIdx.x * M_TILE + w * 16;
    const int row16 = lane & 15;
    const int mrow = wbase + row16;
    const bool vrow = mrow < kMVox;

    const uint32_t s0 = (uint32_t)__cvta_generic_to_shared(stage[0][w]);
    const uint32_t s1 = (uint32_t)__cvta_generic_to_shared(stage[1][w]);

    // masked idx for this warp's 16 rows, replicated in lanes r and r+16
    auto ldidx = [&](int k) -> int {
        size_t off = (size_t)k * kMVox;
        int x = 0;
        if (vrow) x = (lane < 16) ? in_idx[off + mrow] : mask[off + mrow];
        int other = __shfl_xor_sync(0xffffffffu, x, 16);
        int ix = (lane < 16) ? x : other;
        int mk = (lane < 16) ? other : x;
        return (vrow && mk) ? ix : -1;
    };

    // stage 16 rows (128B each) via cp.async; 4 chunks of 16B per lane
    auto cp_stage = [&](uint32_t sbase, int v) {
#pragma unroll
        for (int j = 0; j < 4; ++j) {
            int r = j * 4 + (lane >> 3);
            int c = lane & 7;
            int ir = __shfl_sync(0xffffffffu, v, r);
            const float* src = feats + (size_t)(ir < 0 ? 0 : ir) * kCIn + c * 4;
            uint32_t dst = sbase + r * 128 + ((c ^ (r & 7)) << 4);
            int sz = (ir >= 0) ? 16 : 0;
            asm volatile("cp.async.cg.shared.global [%0], [%1], 16, %2;"
                         :: "r"(dst), "l"(src), "r"(sz));
        }
    };

    float acc[8][4];
#pragma unroll
    for (int i = 0; i < 8; ++i)
#pragma unroll
        for (int j = 0; j < 4; ++j) acc[i][j] = 0.f;

    // --- prologue: stage k=0,1; idx for k=2 in flight ---
    {
        int v = ldidx(0);
        cp_stage(s0, v);
        asm volatile("cp.async.commit_group;" ::: "memory");
        v = ldidx(1);
        cp_stage(s1, v);
        asm volatile("cp.async.commit_group;" ::: "memory");
    }
    int vnext = ldidx(2);

    // swizzled read offsets for this lane (rows g and g+8, chunks 2t, 2t+1)
    const uint32_t oA0 = g * 128 + (((2 * t) ^ (g & 7)) << 4);
    const uint32_t oA1 = g * 128 + (((2 * t + 1) ^ (g & 7)) << 4);
    const uint32_t oB0 = (g + 8) * 128 + (((2 * t) ^ (g & 7)) << 4);
    const uint32_t oB1 = (g + 8) * 128 + (((2 * t + 1) ^ (g & 7)) << 4);

#pragma unroll 1
    for (int koff = 0; koff < kKVol; ++koff) {
        asm volatile("cp.async.wait_group 1;" ::: "memory");
        __syncwarp();
        const uint32_t sb = (koff & 1) ? s1 : s0;

        float4 rA0 = lds128(sb + oA0);
        float4 rA1 = lds128(sb + oA1);
        float4 rB0 = lds128(sb + oB0);
        float4 rB1 = lds128(sb + oB1);

        // converts consume LDS data -> guarantee reads done before the
        // same-buffer cp.async below can issue (in-order issue per warp)
        unsigned ak0[4], ak1[4];
        ak0[0] = f16x2(rA0.x, rA0.y);
        ak0[1] = f16x2(rB0.x, rB0.y);
        ak0[2] = f16x2(rA0.z, rA0.w);
        ak0[3] = f16x2(rB0.z, rB0.w);
        ak1[0] = f16x2(rA1.x, rA1.y);
        ak1[1] = f16x2(rB1.x, rB1.y);
        ak1[2] = f16x2(rA1.z, rA1.w);
        ak1[3] = f16x2(rB1.z, rB1.w);

        if (koff + 2 < kKVol) cp_stage(sb, vnext);
        asm volatile("cp.async.commit_group;" ::: "memory");
        if (koff + 3 < kKVol) vnext = ldidx(koff + 3);

        const uint4* bp = g_bfrag + (size_t)koff * 8 * 32 + lane;
#pragma unroll
        for (int nb = 0; nb < 8; ++nb) {
            uint4 bw = bp[nb * 32];
            mma16816(acc[nb], ak0, bw.x, bw.y);
            mma16816(acc[nb], ak1, bw.z, bw.w);
        }
    }

    // store: d0,d1 -> row wbase+g ; d2,d3 -> row wbase+g+8
    const int mA = wbase + g, mB = wbase + g + 8;
#pragma unroll
    for (int nb = 0; nb < 8; ++nb) {
        int n = nb * 8 + 2 * t;
        if (mA < kMVox)
            *(float2*)(out + (size_t)mA * kCOut + n) = make_float2(acc[nb][0], acc[nb][1]);
        if (mB < kMVox)
            *(float2*)(out + (size_t)mB * kCOut + n) = make_float2(acc[nb][2], acc[nb][3]);
    }
}

extern "C" void kernel_launch(void* const* d_in, const int* in_sizes, int n_in,
                              void* d_out, int out_size) {
    const float* feats  = (const float*)d_in[0];
    const float* kernel = (const float*)d_in[1];
    const int*   in_idx = (const int*)d_in[2];
    const int*   maskp  = (const int*)d_in[3];
    float*       out    = (float*)d_out;
    (void)in_sizes; (void)n_in; (void)out_size;

    prep_kernel<<<kKVol, 256>>>(kernel);
    int grid = (kMVox + M_TILE - 1) / M_TILE;   // 782
    conv_hmma_kernel<<<grid, 256>>>(feats, in_idx, maskp, out);
}

// round 9
// speedup vs baseline: 1.0862x; 1.0862x over previous
#include <cuda_runtime.h>
#include <cstdint>

// Sparse 3D conv via warp-level fp16 mma.sync (m16n8k16), single pass.
// R9 = R6 (best: register pipeline, no smem) + L1 prefetch of the k+2 gather
// rows (prefetch.global.L1: no dest register, no scoreboard) driven by a
// rolling idx pair, so the k+1 row loads become L1 hits (~39cyc) and the
// per-iteration long-scoreboard stall at the converts disappears.

static constexpr int kMVox = 100000;
static constexpr int kKVol = 27;
static constexpr int kCIn  = 32;
static constexpr int kCOut = 64;
static constexpr int M_TILE = 128;     // 8 warps x 16 rows

// B fragments, fp16, fragment-order with K-permutation:
// [koff][nb][lane] -> uint4 {ks0.b0, ks0.b1, ks1.b0, ks1.b1}
// word j of lane(g,t) = f16x2( W[8t+2j][n], W[8t+2j+1][n] ), n = nb*8+g
__device__ __align__(16) uint4 g_bfrag[kKVol * 8 * 32];

__device__ __forceinline__ unsigned f16x2(float x, float y) {
    unsigned r;
    asm("cvt.rn.f16x2.f32 %0, %1, %2;" : "=r"(r) : "f"(y), "f"(x));  // x -> low half
    return r;
}

__global__ void prep_kernel(const float* __restrict__ kw) {
    int koff = blockIdx.x, tid = threadIdx.x;       // 27 x 256
    int nb = tid >> 5, lane = tid & 31;
    int g = lane >> 2, t = lane & 3;
    int n = nb * 8 + g;
    const float* W = kw + koff * kCIn * kCOut;      // W[i][n]
    uint4 v;
    v.x = f16x2(W[(8 * t + 0) * kCOut + n], W[(8 * t + 1) * kCOut + n]);
    v.y = f16x2(W[(8 * t + 2) * kCOut + n], W[(8 * t + 3) * kCOut + n]);
    v.z = f16x2(W[(8 * t + 4) * kCOut + n], W[(8 * t + 5) * kCOut + n]);
    v.w = f16x2(W[(8 * t + 6) * kCOut + n], W[(8 * t + 7) * kCOut + n]);
    g_bfrag[(koff * 8 + nb) * 32 + lane] = v;
}

__device__ __forceinline__ void mma16816(float* d, const unsigned* a,
                                         unsigned b0, unsigned b1) {
    asm volatile(
        "mma.sync.aligned.m16n8k16.row.col.f32.f16.f16.f32 "
        "{%0,%1,%2,%3}, {%4,%5,%6,%7}, {%8,%9}, {%0,%1,%2,%3};"
        : "+f"(d[0]), "+f"(d[1]), "+f"(d[2]), "+f"(d[3])
        : "r"(a[0]), "r"(a[1]), "r"(a[2]), "r"(a[3]), "r"(b0), "r"(b1));
}

__global__ __launch_bounds__(256, 3)
void conv_hmma_kernel(const float* __restrict__ feats,
                      const int*   __restrict__ in_idx,
                      const int*   __restrict__ mask,
                      float*       __restrict__ out) {
    const int w = threadIdx.x >> 5, lane = threadIdx.x & 31;
    const int g = lane >> 2, t = lane & 3;
    const int mbase = blockIdx.x * M_TILE + w * 16;
    const int mA = mbase + g;        // fragment rows g
    const int mB = mbase + g + 8;    // fragment rows g+8
    const bool vA = mA < kMVox, vB = mB < kMVox;

    // masked idx pair for offset k (independent loads, select after)
    auto ldidx = [&](int k, int& o0, int& o1) {
        size_t off = (size_t)k * kMVox;
        int mk0 = vA ? mask[off + mA] : 0;
        int ix0 = vA ? in_idx[off + mA] : 0;
        int mk1 = vB ? mask[off + mB] : 0;
        int ix1 = vB ? in_idx[off + mB] : 0;
        o0 = mk0 ? ix0 : -1;
        o1 = mk1 ? ix1 : -1;
    };

    float acc[8][4];
#pragma unroll
    for (int i = 0; i < 8; ++i)
#pragma unroll
        for (int j = 0; j < 4; ++j) acc[i][j] = 0.f;

    // --- prologue ---
    int i0, i1;                    // idx for k=0
    ldidx(0, i0, i1);
    float4 rA0, rA1, rB0, rB1;     // raw rows for current k
    {
        const float4* pA = (const float4*)(feats + (size_t)(i0 < 0 ? 0 : i0) * kCIn);
        const float4* pB = (const float4*)(feats + (size_t)(i1 < 0 ? 0 : i1) * kCIn);
        float4 z = make_float4(0.f, 0.f, 0.f, 0.f);
        rA0 = (i0 >= 0) ? pA[2 * t] : z;
        rA1 = (i0 >= 0) ? pA[2 * t + 1] : z;
        rB0 = (i1 >= 0) ? pB[2 * t] : z;
        rB1 = (i1 >= 0) ? pB[2 * t + 1] : z;
    }
    int a0, a1;                    // idx for k+1 (arrives first)
    int b0i, b1i;                  // idx for k+2 (in flight)
    ldidx(1, a0, a1);
    ldidx(2, b0i, b1i);

#pragma unroll 1
    for (int koff = 0; koff < kKVol; ++koff) {
        // --- convert current raw rows to fragments ---
        unsigned ak0[4], ak1[4];
        ak0[0] = f16x2(rA0.x, rA0.y);   // ks0 a0 (row g)
        ak0[1] = f16x2(rB0.x, rB0.y);   // ks0 a1 (row g+8)
        ak0[2] = f16x2(rA0.z, rA0.w);   // ks0 a2
        ak0[3] = f16x2(rB0.z, rB0.w);   // ks0 a3
        ak1[0] = f16x2(rA1.x, rA1.y);   // ks1 a0
        ak1[1] = f16x2(rB1.x, rB1.y);   // ks1 a1
        ak1[2] = f16x2(rA1.z, rA1.w);   // ks1 a2
        ak1[3] = f16x2(rB1.z, rB1.w);   // ks1 a3

        // --- issue rows for k+1 (L1 hits: prefetched last iteration) ---
        if (koff + 1 < kKVol) {
            const float4* pA = (const float4*)(feats + (size_t)(a0 < 0 ? 0 : a0) * kCIn);
            const float4* pB = (const float4*)(feats + (size_t)(a1 < 0 ? 0 : a1) * kCIn);
            float4 z = make_float4(0.f, 0.f, 0.f, 0.f);
            rA0 = (a0 >= 0) ? pA[2 * t] : z;
            rA1 = (a0 >= 0) ? pA[2 * t + 1] : z;
            rB0 = (a1 >= 0) ? pB[2 * t] : z;
            rB1 = (a1 >= 0) ? pB[2 * t + 1] : z;
        }

        // --- MMA block: 8 n-blocks x 2 k-steps (latency cover) ---
        const uint4* bp = g_bfrag + (size_t)koff * 8 * 32 + lane;
#pragma unroll
        for (int nb = 0; nb < 8; ++nb) {
            uint4 bw = bp[nb * 32];
            mma16816(acc[nb], ak0, bw.x, bw.y);
            mma16816(acc[nb], ak1, bw.z, bw.w);
        }

        // --- prefetch rows for k+2 into L1 (idx b* arrived ~1 iter ago) ---
        // one 128B line per row; t==0 lanes cover all 16 rows of the warp
        if (koff + 2 < kKVol && t == 0) {
            if (b0i >= 0)
                asm volatile("prefetch.global.L1 [%0];"
                             :: "l"(feats + (size_t)b0i * kCIn));
            if (b1i >= 0)
                asm volatile("prefetch.global.L1 [%0];"
                             :: "l"(feats + (size_t)b1i * kCIn));
        }
        // rotate idx pipeline, issue idx for k+3
        a0 = b0i; a1 = b1i;
        if (koff + 3 < kKVol) ldidx(koff + 3, b0i, b1i);
    }

    // store: d0,d1 -> row mA cols nb*8+2t..+1 ; d2,d3 -> row mB
#pragma unroll
    for (int nb = 0; nb < 8; ++nb) {
        int n = nb * 8 + 2 * t;
        if (vA)
            *(float2*)(out + (size_t)mA * kCOut + n) = make_float2(acc[nb][0], acc[nb][1]);
        if (vB)
            *(float2*)(out + (size_t)mB * kCOut + n) = make_float2(acc[nb][2], acc[nb][3]);
    }
}

extern "C" void kernel_launch(void* const* d_in, const int* in_sizes, int n_in,
                              void* d_out, int out_size) {
    const float* feats  = (const float*)d_in[0];
    const float* kernel = (const float*)d_in[1];
    const int*   in_idx = (const int*)d_in[2];
    const int*   maskp  = (const int*)d_in[3];
    float*       out    = (float*)d_out;
    (void)in_sizes; (void)n_in; (void)out_size;

    prep_kernel<<<kKVol, 256>>>(kernel);
    int grid = (kMVox + M_TILE - 1) / M_TILE;   // 782
    conv_hmma_kernel<<<grid, 256>>>(feats, in_idx, maskp, out);
}